// round 1
// baseline (speedup 1.0000x reference)
#include <cuda_runtime.h>
#include <math.h>

#define BB 4
#define T 1024
#define D 512
#define H 8
#define DKK 64
#define LL 2047
#define BT (BB*T)      // 4096
#define BL (BB*LL)     // 8188

// scratch (device globals: allocation-free)
__device__ float g_y[BT*D];
__device__ float g_q[BT*D];
__device__ float g_k[BT*D];
__device__ float g_v[BT*D];
__device__ float g_p[BL*D];
__device__ float g_o[BT*D];
__device__ float g_s[(size_t)BB*H*T*T];   // 128MB scores

// ---------------- LayerNorm ----------------
__global__ void ln_kernel(const float* __restrict__ x,
                          const float* __restrict__ gamma,
                          const float* __restrict__ beta) {
    int row = blockIdx.x;
    const float* xr = x + (size_t)row * D;
    float* yr = g_y + (size_t)row * D;
    int t = threadIdx.x;  // 256
    float v0 = xr[t], v1 = xr[t + 256];
    float s = v0 + v1, sq = v0 * v0 + v1 * v1;
    __shared__ float ss[8], ssq[8], mb[2];
    #pragma unroll
    for (int o = 16; o > 0; o >>= 1) {
        s  += __shfl_xor_sync(0xFFFFFFFFu, s, o);
        sq += __shfl_xor_sync(0xFFFFFFFFu, sq, o);
    }
    if ((t & 31) == 0) { ss[t >> 5] = s; ssq[t >> 5] = sq; }
    __syncthreads();
    if (t == 0) {
        float S = 0.f, SQ = 0.f;
        #pragma unroll
        for (int i = 0; i < 8; i++) { S += ss[i]; SQ += ssq[i]; }
        float mean = S * (1.0f / D);
        float var = SQ * (1.0f / D) - mean * mean;
        mb[0] = mean;
        mb[1] = rsqrtf(var + 1e-3f);
    }
    __syncthreads();
    float mean = mb[0], rstd = mb[1];
    yr[t]       = (v0 - mean) * rstd * gamma[t]       + beta[t];
    yr[t + 256] = (v1 - mean) * rstd * gamma[t + 256] + beta[t + 256];
}

// ---------------- generic [M,512] x [512,512] SGEMM (+bias, +residual) ----------------
__global__ void sgemm512(const float* __restrict__ A, const float* __restrict__ W,
                         const float* __restrict__ bias, const float* __restrict__ res,
                         float* __restrict__ C, int M) {
    __shared__ float As[16][68];
    __shared__ float Bs[16][68];
    int tid = threadIdx.x;
    int i0 = blockIdx.y * 64, j0 = blockIdx.x * 64;
    float acc[4][4] = {};
    int tx = tid & 15, ty = tid >> 4;
    for (int kk = 0; kk < 512; kk += 16) {
        #pragma unroll
        for (int r = 0; r < 4; r++) {
            int idx = r * 256 + tid;
            int m = idx >> 4, k = idx & 15;
            int gm = i0 + m;
            As[k][m] = (gm < M) ? A[(size_t)gm * 512 + kk + k] : 0.f;
        }
        #pragma unroll
        for (int r = 0; r < 4; r++) {
            int idx = r * 256 + tid;
            int n = idx & 63, k = idx >> 6;
            Bs[k][n] = W[(size_t)(kk + k) * 512 + j0 + n];
        }
        __syncthreads();
        #pragma unroll
        for (int k = 0; k < 16; k++) {
            float4 a4 = *(const float4*)&As[k][ty * 4];
            float4 b4 = *(const float4*)&Bs[k][tx * 4];
            float av[4] = {a4.x, a4.y, a4.z, a4.w};
            float bv[4] = {b4.x, b4.y, b4.z, b4.w};
            #pragma unroll
            for (int r = 0; r < 4; r++)
                #pragma unroll
                for (int c = 0; c < 4; c++)
                    acc[r][c] = fmaf(av[r], bv[c], acc[r][c]);
        }
        __syncthreads();
    }
    #pragma unroll
    for (int r = 0; r < 4; r++) {
        int gm = i0 + ty * 4 + r;
        if (gm >= M) break;
        #pragma unroll
        for (int c = 0; c < 4; c++) {
            int gn = j0 + tx * 4 + c;
            float v = acc[r][c];
            if (bias) v += bias[gn];
            if (res)  v += res[(size_t)gm * 512 + gn];
            C[(size_t)gm * 512 + gn] = v;
        }
    }
}

// ---------------- positional scores in diagonal coords (writes g_s) ----------------
// pos_shifted[i,j] = dot(q[i]+pb, p[1024 + (j-i)])   (l=2047 special-cased by fix_kernel)
__global__ void pos_kernel(const float* __restrict__ pb) {
    int z = blockIdx.z; int b = z >> 3, h = z & 7;
    int i0 = blockIdx.y * 64;
    int d0 = blockIdx.x * 64 - 1024;
    // tile valid iff some j = i+d in [0,T)
    if (i0 + d0 > T - 1 || i0 + d0 + 126 < 0) return;
    __shared__ float Qs[64][68], Ps[64][68], pbs[64];
    int tid = threadIdx.x;
    const float* qb = g_q + ((size_t)(b * T + i0)) * D + h * DKK;
    #pragma unroll
    for (int r = 0; r < 16; r++) {
        int idx = r * 256 + tid;
        int m = idx >> 6, kk = idx & 63;
        Qs[kk][m] = qb[(size_t)m * D + kk];
        int l = 1024 + d0 + m;
        if (l < 0) l = 0;
        if (l > LL - 1) l = LL - 1;   // overflow slot handled by fix_kernel
        Ps[kk][m] = g_p[((size_t)(b * LL + l)) * D + h * DKK + kk];
    }
    if (tid < 64) pbs[tid] = pb[h * DKK + tid];
    __syncthreads();
    int tx = tid & 15, ty = tid >> 4;
    float acc[4][4] = {};
    #pragma unroll 8
    for (int k = 0; k < 64; k++) {
        float4 a4 = *(const float4*)&Qs[k][ty * 4];
        float4 b4 = *(const float4*)&Ps[k][tx * 4];
        float pbk = pbs[k];
        float av[4] = {a4.x + pbk, a4.y + pbk, a4.z + pbk, a4.w + pbk};
        float bv[4] = {b4.x, b4.y, b4.z, b4.w};
        #pragma unroll
        for (int r = 0; r < 4; r++)
            #pragma unroll
            for (int c = 0; c < 4; c++)
                acc[r][c] = fmaf(av[r], bv[c], acc[r][c]);
    }
    #pragma unroll
    for (int r = 0; r < 4; r++) {
        int i = i0 + ty * 4 + r;
        #pragma unroll
        for (int c = 0; c < 4; c++) {
            int d = d0 + tx * 4 + c;
            int j = i + d;
            if (j >= 0 && j < T)
                g_s[((size_t)z * T + i) * T + j] = acc[r][c];
        }
    }
}

// special element: scores_pos[b,h,0,T-1] = dot(q[b,1,h]+pb[h], p[b,0,h])
__global__ void fix_kernel(const float* __restrict__ pb) {
    int z = blockIdx.x; int b = z >> 3, h = z & 7;
    int t = threadIdx.x;  // 32
    float s = 0.f;
    #pragma unroll
    for (int kk = t; kk < 64; kk += 32)
        s += (g_q[((size_t)(b * T + 1)) * D + h * DKK + kk] + pb[h * DKK + kk]) *
             g_p[((size_t)(b * LL + 0)) * D + h * DKK + kk];
    #pragma unroll
    for (int o = 16; o > 0; o >>= 1) s += __shfl_xor_sync(0xFFFFFFFFu, s, o);
    if (t == 0)
        g_s[((size_t)z * T + 0) * T + (T - 1)] = s;
}

// ---------------- content scores (adds into g_s) ----------------
__global__ void content_kernel(const float* __restrict__ cb) {
    int z = blockIdx.z; int b = z >> 3, h = z & 7;
    int i0 = blockIdx.y * 64, j0 = blockIdx.x * 64;
    __shared__ float Qs[64][68], Ks[64][68], cbs[64];
    int tid = threadIdx.x;
    const float* qb = g_q + ((size_t)(b * T + i0)) * D + h * DKK;
    const float* kb = g_k + ((size_t)(b * T + j0)) * D + h * DKK;
    #pragma unroll
    for (int r = 0; r < 16; r++) {
        int idx = r * 256 + tid;
        int m = idx >> 6, kk = idx & 63;
        Qs[kk][m] = qb[(size_t)m * D + kk];
        Ks[kk][m] = kb[(size_t)m * D + kk];
    }
    if (tid < 64) cbs[tid] = cb[h * DKK + tid];
    __syncthreads();
    int tx = tid & 15, ty = tid >> 4;
    float acc[4][4] = {};
    #pragma unroll 8
    for (int k = 0; k < 64; k++) {
        float4 a4 = *(const float4*)&Qs[k][ty * 4];
        float4 b4 = *(const float4*)&Ks[k][tx * 4];
        float cbk = cbs[k];
        float av[4] = {a4.x + cbk, a4.y + cbk, a4.z + cbk, a4.w + cbk};
        float bv[4] = {b4.x, b4.y, b4.z, b4.w};
        #pragma unroll
        for (int r = 0; r < 4; r++)
            #pragma unroll
            for (int c = 0; c < 4; c++)
                acc[r][c] = fmaf(av[r], bv[c], acc[r][c]);
    }
    float* sp = g_s + ((size_t)z * T + i0) * T + j0;
    #pragma unroll
    for (int r = 0; r < 4; r++) {
        float4* dst = (float4*)&sp[(size_t)(ty * 4 + r) * T + tx * 4];
        float4 old = *dst;
        old.x += acc[r][0]; old.y += acc[r][1];
        old.z += acc[r][2]; old.w += acc[r][3];
        *dst = old;
    }
}

// ---------------- softmax over rows of g_s (with 1/sqrt(DK) scale) ----------------
__global__ void softmax_kernel() {
    size_t row = blockIdx.x;
    float* sr = g_s + row * T;
    int t = threadIdx.x;  // 256
    float4 v = *(float4*)&sr[t * 4];
    const float sc = 0.125f;  // 1/sqrt(64)
    v.x *= sc; v.y *= sc; v.z *= sc; v.w *= sc;
    float mx = fmaxf(fmaxf(v.x, v.y), fmaxf(v.z, v.w));
    __shared__ float red[8];
    #pragma unroll
    for (int o = 16; o > 0; o >>= 1) mx = fmaxf(mx, __shfl_xor_sync(0xFFFFFFFFu, mx, o));
    if ((t & 31) == 0) red[t >> 5] = mx;
    __syncthreads();
    float m0 = red[0];
    #pragma unroll
    for (int i = 1; i < 8; i++) m0 = fmaxf(m0, red[i]);
    __syncthreads();
    float e0 = expf(v.x - m0), e1 = expf(v.y - m0);
    float e2 = expf(v.z - m0), e3 = expf(v.w - m0);
    float s = e0 + e1 + e2 + e3;
    #pragma unroll
    for (int o = 16; o > 0; o >>= 1) s += __shfl_xor_sync(0xFFFFFFFFu, s, o);
    if ((t & 31) == 0) red[t >> 5] = s;
    __syncthreads();
    float S = 0.f;
    #pragma unroll
    for (int i = 0; i < 8; i++) S += red[i];
    float inv = 1.0f / S;
    v.x = e0 * inv; v.y = e1 * inv; v.z = e2 * inv; v.w = e3 * inv;
    *(float4*)&sr[t * 4] = v;
}

// ---------------- attn @ v -> g_o ----------------
__global__ void av_kernel() {
    int z = blockIdx.y; int b = z >> 3, h = z & 7;
    int i0 = blockIdx.x * 64;
    __shared__ float As[32][68], Bs[32][68];
    int tid = threadIdx.x;
    int tx = tid & 15, ty = tid >> 4;
    float acc[4][4] = {};
    const float* sp = g_s + ((size_t)z * T + i0) * T;
    const float* vp = g_v + (size_t)(b * T) * D + h * DKK;
    for (int kk = 0; kk < T; kk += 32) {
        #pragma unroll
        for (int r = 0; r < 8; r++) {
            int idx = r * 256 + tid;
            int m = idx >> 5, k = idx & 31;
            As[k][m] = sp[(size_t)m * T + kk + k];
            int n = idx & 63, k2 = idx >> 6;
            Bs[k2][n] = vp[(size_t)(kk + k2) * D + n];
        }
        __syncthreads();
        #pragma unroll
        for (int k = 0; k < 32; k++) {
            float4 a4 = *(const float4*)&As[k][ty * 4];
            float4 b4 = *(const float4*)&Bs[k][tx * 4];
            float av[4] = {a4.x, a4.y, a4.z, a4.w};
            float bv[4] = {b4.x, b4.y, b4.z, b4.w};
            #pragma unroll
            for (int r = 0; r < 4; r++)
                #pragma unroll
                for (int c = 0; c < 4; c++)
                    acc[r][c] = fmaf(av[r], bv[c], acc[r][c]);
        }
        __syncthreads();
    }
    #pragma unroll
    for (int r = 0; r < 4; r++) {
        float4 o4 = make_float4(acc[r][0], acc[r][1], acc[r][2], acc[r][3]);
        *(float4*)&g_o[((size_t)(b * T + i0 + ty * 4 + r)) * D + h * DKK + tx * 4] = o4;
    }
}

extern "C" void kernel_launch(void* const* d_in, const int* in_sizes, int n_in,
                              void* d_out, int out_size) {
    const float* x     = (const float*)d_in[0];
    const float* pos   = (const float*)d_in[1];
    const float* cb    = (const float*)d_in[2];
    const float* pb    = (const float*)d_in[3];
    const float* gamma = (const float*)d_in[4];
    const float* beta  = (const float*)d_in[5];
    const float* Wq    = (const float*)d_in[6];
    const float* bq    = (const float*)d_in[7];
    const float* Wk    = (const float*)d_in[8];
    const float* bk    = (const float*)d_in[9];
    const float* Wv    = (const float*)d_in[10];
    const float* bv    = (const float*)d_in[11];
    const float* Wp    = (const float*)d_in[12];
    const float* Wo    = (const float*)d_in[13];
    const float* bo    = (const float*)d_in[14];
    float* out = (float*)d_out;

    float *y, *q, *k, *v, *p, *o;
    cudaGetSymbolAddress((void**)&y, g_y);
    cudaGetSymbolAddress((void**)&q, g_q);
    cudaGetSymbolAddress((void**)&k, g_k);
    cudaGetSymbolAddress((void**)&v, g_v);
    cudaGetSymbolAddress((void**)&p, g_p);
    cudaGetSymbolAddress((void**)&o, g_o);

    // 1. LayerNorm
    ln_kernel<<<BT, 256>>>(x, gamma, beta);

    // 2. projections
    dim3 gq(8, BT / 64);
    sgemm512<<<gq, 256>>>(y, Wq, bq, nullptr, q, BT);
    sgemm512<<<gq, 256>>>(y, Wk, bk, nullptr, k, BT);
    sgemm512<<<gq, 256>>>(y, Wv, bv, nullptr, v, BT);
    dim3 gp(8, (BL + 63) / 64);
    sgemm512<<<gp, 256>>>(pos, Wp, nullptr, nullptr, p, BL);

    // 3. scores: positional (write, banded diag-GEMM) -> fix special -> content (add)
    pos_kernel<<<dim3(32, 16, BB * H), 256>>>(pb);
    fix_kernel<<<BB * H, 32>>>(pb);
    content_kernel<<<dim3(16, 16, BB * H), 256>>>(cb);

    // 4. softmax (with 1/8 scale)
    softmax_kernel<<<BB * H * T, 256>>>();

    // 5. attn @ v
    av_kernel<<<dim3(16, BB * H), 256>>>();

    // 6. output projection + bias + residual
    sgemm512<<<gq, 256>>>(o, Wo, bo, x, out, BT);
}

// round 2
// speedup vs baseline: 1.9596x; 1.9596x over previous
#include <cuda_runtime.h>
#include <math.h>

#define BB 4
#define T 1024
#define D 512
#define H 8
#define DKK 64
#define LL 2047
#define BT (BB*T)      // 4096
#define BL (BB*LL)     // 8188

// scratch
__device__ float g_y[BT*D];
__device__ float g_qc[BT*D];   // q + bq + content_bias
__device__ float g_qp[BT*D];   // q + bq + pos_bias
__device__ float g_k[BT*D];
__device__ float g_v[BT*D];
__device__ float g_p[BL*D];
__device__ float g_o[BT*D];
__device__ float g_s[(size_t)BB*H*T*T];   // 128MB scores

// ---------------- mma helpers ----------------
__device__ __forceinline__ unsigned f2tf(float f) {
    unsigned u; asm("cvt.rna.tf32.f32 %0, %1;" : "=r"(u) : "f"(f)); return u;
}
__device__ __forceinline__ void mma_tf32(float d[4], const unsigned a[4], const unsigned b[2]) {
    asm volatile("mma.sync.aligned.m16n8k8.row.col.f32.tf32.tf32.f32 "
        "{%0,%1,%2,%3},{%4,%5,%6,%7},{%8,%9},{%0,%1,%2,%3};\n"
        : "+f"(d[0]), "+f"(d[1]), "+f"(d[2]), "+f"(d[3])
        : "r"(a[0]), "r"(a[1]), "r"(a[2]), "r"(a[3]), "r"(b[0]), "r"(b[1]));
}

// ---------------- LayerNorm ----------------
__global__ void ln_kernel(const float* __restrict__ x,
                          const float* __restrict__ gamma,
                          const float* __restrict__ beta) {
    int row = blockIdx.x;
    const float* xr = x + (size_t)row * D;
    float* yr = g_y + (size_t)row * D;
    int t = threadIdx.x;  // 256
    float v0 = xr[t], v1 = xr[t + 256];
    float s = v0 + v1, sq = v0 * v0 + v1 * v1;
    __shared__ float ss[8], ssq[8], mb[2];
    #pragma unroll
    for (int o = 16; o > 0; o >>= 1) {
        s  += __shfl_xor_sync(0xFFFFFFFFu, s, o);
        sq += __shfl_xor_sync(0xFFFFFFFFu, sq, o);
    }
    if ((t & 31) == 0) { ss[t >> 5] = s; ssq[t >> 5] = sq; }
    __syncthreads();
    if (t == 0) {
        float S = 0.f, SQ = 0.f;
        #pragma unroll
        for (int i = 0; i < 8; i++) { S += ss[i]; SQ += ssq[i]; }
        float mean = S * (1.0f / D);
        float var = SQ * (1.0f / D) - mean * mean;
        mb[0] = mean;
        mb[1] = rsqrtf(var + 1e-3f);
    }
    __syncthreads();
    float mean = mb[0], rstd = mb[1];
    yr[t]       = (v0 - mean) * rstd * gamma[t]       + beta[t];
    yr[t + 256] = (v1 - mean) * rstd * gamma[t + 256] + beta[t + 256];
}

// ---------------- tf32 GEMM: C[M,512] = A[M,512]@W[512,512] (+bias/extras/res) ----------------
// block 128x128, 256 thr, 8 warps (2M x 4N), warp tile 64x32
__global__ void proj_mma(const float* __restrict__ A, const float* __restrict__ W,
                         const float* __restrict__ bias1,
                         const float* __restrict__ extra1, const float* __restrict__ extra2,
                         const float* __restrict__ res,
                         float* __restrict__ C1, float* __restrict__ C2, int M) {
    __shared__ unsigned As[128][36];
    __shared__ unsigned Bs[32][136];
    int tid = threadIdx.x;
    int warp = tid >> 5, lane = tid & 31;
    int i0 = blockIdx.y * 128, j0 = blockIdx.x * 128;
    int wy = warp >> 2, wx = warp & 3;
    int g = lane >> 2, q = lane & 3;
    float acc[4][4][4] = {};

    for (int kk = 0; kk < 512; kk += 32) {
        #pragma unroll
        for (int p = 0; p < 4; p++) {
            int m = p * 32 + (tid >> 3);
            int c4 = (tid & 7) * 4;
            int gm = i0 + m;
            float4 v = (gm < M) ? *(const float4*)&A[(size_t)gm * 512 + kk + c4]
                                : make_float4(0.f, 0.f, 0.f, 0.f);
            uint4 u = { f2tf(v.x), f2tf(v.y), f2tf(v.z), f2tf(v.w) };
            *(uint4*)&As[m][c4] = u;
        }
        #pragma unroll
        for (int p = 0; p < 4; p++) {
            int k = p * 8 + (tid >> 5);
            int c4 = (tid & 31) * 4;
            float4 v = *(const float4*)&W[(size_t)(kk + k) * 512 + j0 + c4];
            uint4 u = { f2tf(v.x), f2tf(v.y), f2tf(v.z), f2tf(v.w) };
            *(uint4*)&Bs[k][c4] = u;
        }
        __syncthreads();
        #pragma unroll
        for (int k8 = 0; k8 < 4; k8++) {
            int kc = k8 * 8 + q;
            unsigned af[4][4], bf[4][2];
            #pragma unroll
            for (int mt = 0; mt < 4; mt++) {
                int r = wy * 64 + mt * 16;
                af[mt][0] = As[r + g][kc];     af[mt][1] = As[r + g + 8][kc];
                af[mt][2] = As[r + g][kc + 4]; af[mt][3] = As[r + g + 8][kc + 4];
            }
            #pragma unroll
            for (int nt = 0; nt < 4; nt++) {
                int c = wx * 32 + nt * 8 + g;
                bf[nt][0] = Bs[kc][c]; bf[nt][1] = Bs[kc + 4][c];
            }
            #pragma unroll
            for (int mt = 0; mt < 4; mt++)
                #pragma unroll
                for (int nt = 0; nt < 4; nt++)
                    mma_tf32(acc[mt][nt], af[mt], bf[nt]);
        }
        __syncthreads();
    }
    #pragma unroll
    for (int mt = 0; mt < 4; mt++) {
        #pragma unroll
        for (int nt = 0; nt < 4; nt++) {
            int c = j0 + wx * 32 + nt * 8 + q * 2;
            float b0 = bias1 ? bias1[c] : 0.f;
            float b1 = bias1 ? bias1[c + 1] : 0.f;
            #pragma unroll
            for (int half = 0; half < 2; half++) {
                int rr = i0 + wy * 64 + mt * 16 + g + half * 8;
                if (rr >= M) continue;
                float e0 = acc[mt][nt][half * 2 + 0] + b0;
                float e1 = acc[mt][nt][half * 2 + 1] + b1;
                if (res) { e0 += res[(size_t)rr * 512 + c]; e1 += res[(size_t)rr * 512 + c + 1]; }
                float o0 = e0, o1 = e1;
                if (extra1) { o0 += extra1[c]; o1 += extra1[c + 1]; }
                *(float2*)&C1[(size_t)rr * 512 + c] = make_float2(o0, o1);
                if (C2) {
                    *(float2*)&C2[(size_t)rr * 512 + c] =
                        make_float2(e0 + extra2[c], e1 + extra2[c + 1]);
                }
            }
        }
    }
}

// ---------------- fused content+positional scores ----------------
// per block: (b,h), 64(i) x 64(j) tile. content = qc@k^T; pos via 64x127 diag-GEMM + shift.
struct ScoreSmem {
    unsigned Qc[64][68];
    unsigned Qp[64][68];
    unsigned Ks[64][68];
    unsigned Ps[128][68];
    float    R[64][136];
};

__global__ void scores_mma() {
    extern __shared__ char sraw[];
    ScoreSmem* S = (ScoreSmem*)sraw;
    int z = blockIdx.z; int b = z >> 3, h = z & 7;
    int i0 = blockIdx.y * 64, j0 = blockIdx.x * 64;
    int tid = threadIdx.x;
    int warp = tid >> 5, lane = tid & 31;
    int wy = warp >> 1, wx = warp & 1;     // 4(M) x 2(N) warps
    int g = lane >> 2, q = lane & 3;
    int lb = 1024 + j0 - i0 - 63;          // l = lb + idx, idx = jl - il + 63

    const float* qcb = g_qc + ((size_t)(b * T + i0)) * D + h * DKK;
    const float* qpb = g_qp + ((size_t)(b * T + i0)) * D + h * DKK;
    const float* kb  = g_k  + ((size_t)(b * T + j0)) * D + h * DKK;

    #pragma unroll
    for (int p = 0; p < 4; p++) {
        int r = p * 16 + (tid >> 4);
        int c4 = (tid & 15) * 4;
        float4 v;
        v = *(const float4*)&qcb[(size_t)r * D + c4];
        { uint4 u = { f2tf(v.x), f2tf(v.y), f2tf(v.z), f2tf(v.w) }; *(uint4*)&S->Qc[r][c4] = u; }
        v = *(const float4*)&qpb[(size_t)r * D + c4];
        { uint4 u = { f2tf(v.x), f2tf(v.y), f2tf(v.z), f2tf(v.w) }; *(uint4*)&S->Qp[r][c4] = u; }
        v = *(const float4*)&kb[(size_t)r * D + c4];
        { uint4 u = { f2tf(v.x), f2tf(v.y), f2tf(v.z), f2tf(v.w) }; *(uint4*)&S->Ks[r][c4] = u; }
    }
    #pragma unroll
    for (int p = 0; p < 8; p++) {
        int r = p * 16 + (tid >> 4);
        int c4 = (tid & 15) * 4;
        int l = lb + r;
        l = min(max(l, 0), LL - 1);
        float4 v = *(const float4*)&g_p[((size_t)(b * LL + l)) * D + h * DKK + c4];
        uint4 u = { f2tf(v.x), f2tf(v.y), f2tf(v.z), f2tf(v.w) };
        *(uint4*)&S->Ps[r][c4] = u;
    }
    __syncthreads();

    float accC[4][4] = {};   // content: warp tile 16 x 32 (4 n-tiles)
    float accP[8][4] = {};   // pos:     warp tile 16 x 64 (8 n-tiles)
    #pragma unroll
    for (int k8 = 0; k8 < 8; k8++) {
        int kc = k8 * 8 + q;
        int r = wy * 16;
        unsigned ac[4], ap[4];
        ac[0] = S->Qc[r + g][kc];     ac[1] = S->Qc[r + g + 8][kc];
        ac[2] = S->Qc[r + g][kc + 4]; ac[3] = S->Qc[r + g + 8][kc + 4];
        ap[0] = S->Qp[r + g][kc];     ap[1] = S->Qp[r + g + 8][kc];
        ap[2] = S->Qp[r + g][kc + 4]; ap[3] = S->Qp[r + g + 8][kc + 4];
        #pragma unroll
        for (int nt = 0; nt < 4; nt++) {
            int n = wx * 32 + nt * 8 + g;
            unsigned bf[2] = { S->Ks[n][kc], S->Ks[n][kc + 4] };
            mma_tf32(accC[nt], ac, bf);
        }
        #pragma unroll
        for (int nt = 0; nt < 8; nt++) {
            int n = wx * 64 + nt * 8 + g;
            unsigned bf[2] = { S->Ps[n][kc], S->Ps[n][kc + 4] };
            mma_tf32(accP[nt], ap, bf);
        }
    }
    // stash pos result in smem R[i][idx]
    #pragma unroll
    for (int nt = 0; nt < 8; nt++) {
        int col = wx * 64 + nt * 8 + q * 2;
        int row = wy * 16 + g;
        S->R[row][col]     = accP[nt][0];
        S->R[row][col + 1] = accP[nt][1];
        S->R[row + 8][col]     = accP[nt][2];
        S->R[row + 8][col + 1] = accP[nt][3];
    }
    __syncthreads();
    // epilogue: scores = content + shifted pos
    #pragma unroll
    for (int nt = 0; nt < 4; nt++) {
        int jl = wx * 32 + nt * 8 + q * 2;
        #pragma unroll
        for (int half = 0; half < 2; half++) {
            int il = wy * 16 + g + half * 8;
            int idx = jl - il + 63;            // in [0,126]
            int lg = lb + idx;
            float p0 = (lg == 2047)     ? 0.f : S->R[il][idx];
            float p1 = (lg + 1 == 2047) ? 0.f : S->R[il][idx + 1];
            float2 o = make_float2(accC[nt][half * 2 + 0] + p0,
                                   accC[nt][half * 2 + 1] + p1);
            *(float2*)&g_s[((size_t)z * T + i0 + il) * T + j0 + jl] = o;
        }
    }
}

// rel_shift wraparound element: scores[b,h,0,T-1] += dot(qp[b,1,h], p[b,0,h])
__global__ void fix_kernel() {
    int z = blockIdx.x; int b = z >> 3, h = z & 7;
    int t = threadIdx.x;  // 32
    float s = 0.f;
    #pragma unroll
    for (int kk = t; kk < 64; kk += 32)
        s += g_qp[((size_t)(b * T + 1)) * D + h * DKK + kk] *
             g_p[((size_t)(b * LL)) * D + h * DKK + kk];
    #pragma unroll
    for (int o = 16; o > 0; o >>= 1) s += __shfl_xor_sync(0xFFFFFFFFu, s, o);
    if (t == 0)
        g_s[((size_t)z * T) * T + (T - 1)] += s;
}

// ---------------- softmax (with 1/8 scale) ----------------
__global__ void softmax_kernel() {
    size_t row = blockIdx.x;
    float* sr = g_s + row * T;
    int t = threadIdx.x;  // 256
    float4 v = *(float4*)&sr[t * 4];
    const float sc = 0.125f;
    v.x *= sc; v.y *= sc; v.z *= sc; v.w *= sc;
    float mx = fmaxf(fmaxf(v.x, v.y), fmaxf(v.z, v.w));
    __shared__ float red[8];
    #pragma unroll
    for (int o = 16; o > 0; o >>= 1) mx = fmaxf(mx, __shfl_xor_sync(0xFFFFFFFFu, mx, o));
    if ((t & 31) == 0) red[t >> 5] = mx;
    __syncthreads();
    float m0 = red[0];
    #pragma unroll
    for (int i = 1; i < 8; i++) m0 = fmaxf(m0, red[i]);
    __syncthreads();
    float e0 = expf(v.x - m0), e1 = expf(v.y - m0);
    float e2 = expf(v.z - m0), e3 = expf(v.w - m0);
    float s = e0 + e1 + e2 + e3;
    #pragma unroll
    for (int o = 16; o > 0; o >>= 1) s += __shfl_xor_sync(0xFFFFFFFFu, s, o);
    if ((t & 31) == 0) red[t >> 5] = s;
    __syncthreads();
    float S = 0.f;
    #pragma unroll
    for (int i = 0; i < 8; i++) S += red[i];
    float inv = 1.0f / S;
    v.x = e0 * inv; v.y = e1 * inv; v.z = e2 * inv; v.w = e3 * inv;
    *(float4*)&sr[t * 4] = v;
}

// ---------------- attn @ v (tf32 mma) ----------------
// block 128(i) x 64(dk) per (b,h); K=1024 in chunks of 32. 8 warps 4x2, warp 32x32.
__global__ void av_mma() {
    __shared__ unsigned As[128][36];
    __shared__ unsigned Vs[32][72];
    int z = blockIdx.y; int b = z >> 3, h = z & 7;
    int i0 = blockIdx.x * 128;
    int tid = threadIdx.x, warp = tid >> 5, lane = tid & 31;
    int wy = warp >> 1, wx = warp & 1;
    int g = lane >> 2, q = lane & 3;
    float acc[2][4][4] = {};
    const float* sp = g_s + ((size_t)z * T + i0) * T;
    const float* vp = g_v + ((size_t)(b * T)) * D + h * DKK;

    for (int kk = 0; kk < T; kk += 32) {
        #pragma unroll
        for (int p = 0; p < 4; p++) {
            int r = p * 32 + (tid >> 3);
            int c4 = (tid & 7) * 4;
            float4 v = *(const float4*)&sp[(size_t)r * T + kk + c4];
            uint4 u = { f2tf(v.x), f2tf(v.y), f2tf(v.z), f2tf(v.w) };
            *(uint4*)&As[r][c4] = u;
        }
        #pragma unroll
        for (int p = 0; p < 2; p++) {
            int r = p * 16 + (tid >> 4);
            int c4 = (tid & 15) * 4;
            float4 v = *(const float4*)&vp[(size_t)(kk + r) * D + c4];
            uint4 u = { f2tf(v.x), f2tf(v.y), f2tf(v.z), f2tf(v.w) };
            *(uint4*)&Vs[r][c4] = u;
        }
        __syncthreads();
        #pragma unroll
        for (int k8 = 0; k8 < 4; k8++) {
            int kc = k8 * 8 + q;
            unsigned af[2][4];
            #pragma unroll
            for (int mt = 0; mt < 2; mt++) {
                int r = wy * 32 + mt * 16;
                af[mt][0] = As[r + g][kc];     af[mt][1] = As[r + g + 8][kc];
                af[mt][2] = As[r + g][kc + 4]; af[mt][3] = As[r + g + 8][kc + 4];
            }
            #pragma unroll
            for (int nt = 0; nt < 4; nt++) {
                int n = wx * 32 + nt * 8 + g;
                unsigned bf[2] = { Vs[kc][n], Vs[kc + 4][n] };
                #pragma unroll
                for (int mt = 0; mt < 2; mt++)
                    mma_tf32(acc[mt][nt], af[mt], bf);
            }
        }
        __syncthreads();
    }
    #pragma unroll
    for (int mt = 0; mt < 2; mt++)
        #pragma unroll
        for (int nt = 0; nt < 4; nt++) {
            int r = i0 + wy * 32 + mt * 16 + g;
            int c = wx * 32 + nt * 8 + q * 2;
            if (c < 64) {
                *(float2*)&g_o[((size_t)(b * T + r)) * D + h * DKK + c] =
                    make_float2(acc[mt][nt][0], acc[mt][nt][1]);
                *(float2*)&g_o[((size_t)(b * T + r + 8)) * D + h * DKK + c] =
                    make_float2(acc[mt][nt][2], acc[mt][nt][3]);
            }
        }
}

extern "C" void kernel_launch(void* const* d_in, const int* in_sizes, int n_in,
                              void* d_out, int out_size) {
    const float* x     = (const float*)d_in[0];
    const float* pos   = (const float*)d_in[1];
    const float* cb    = (const float*)d_in[2];
    const float* pb    = (const float*)d_in[3];
    const float* gamma = (const float*)d_in[4];
    const float* beta  = (const float*)d_in[5];
    const float* Wq    = (const float*)d_in[6];
    const float* bq    = (const float*)d_in[7];
    const float* Wk    = (const float*)d_in[8];
    const float* bk    = (const float*)d_in[9];
    const float* Wv    = (const float*)d_in[10];
    const float* bv    = (const float*)d_in[11];
    const float* Wp    = (const float*)d_in[12];
    const float* Wo    = (const float*)d_in[13];
    const float* bo    = (const float*)d_in[14];
    float* out = (float*)d_out;

    float *y, *qc, *qp, *k, *v, *p, *o;
    cudaGetSymbolAddress((void**)&y,  g_y);
    cudaGetSymbolAddress((void**)&qc, g_qc);
    cudaGetSymbolAddress((void**)&qp, g_qp);
    cudaGetSymbolAddress((void**)&k,  g_k);
    cudaGetSymbolAddress((void**)&v,  g_v);
    cudaGetSymbolAddress((void**)&p,  g_p);
    cudaGetSymbolAddress((void**)&o,  g_o);

    cudaFuncSetAttribute(scores_mma, cudaFuncAttributeMaxDynamicSharedMemorySize,
                         (int)sizeof(ScoreSmem));

    // 1. LayerNorm
    ln_kernel<<<BT, 256>>>(x, gamma, beta);

    // 2. projections (tf32 mma)
    dim3 g4(4, 32);
    proj_mma<<<g4, 256>>>(y, Wq, bq, cb, pb, nullptr, qc, qp, BT);   // qc,qp
    proj_mma<<<g4, 256>>>(y, Wk, bk, nullptr, nullptr, nullptr, k, nullptr, BT);
    proj_mma<<<g4, 256>>>(y, Wv, bv, nullptr, nullptr, nullptr, v, nullptr, BT);
    proj_mma<<<dim3(4, 64), 256>>>(pos, Wp, nullptr, nullptr, nullptr, nullptr, p, nullptr, BL);

    // 3. fused scores (content + shifted positional), then wraparound fix
    scores_mma<<<dim3(16, 16, 32), 256, sizeof(ScoreSmem)>>>();
    fix_kernel<<<BB * H, 32>>>();

    // 4. softmax
    softmax_kernel<<<BB * H * T, 256>>>();

    // 5. attn @ v
    av_mma<<<dim3(8, 32), 256>>>();

    // 6. output projection + bias + residual
    proj_mma<<<g4, 256>>>(o, Wo, bo, nullptr, nullptr, x, out, nullptr, BT);
}

// round 3
// speedup vs baseline: 2.5372x; 1.2947x over previous
#include <cuda_runtime.h>
#include <math.h>

#define BB 4
#define T 1024
#define D 512
#define H 8
#define DKK 64
#define LL 2047
#define BT (BB*T)      // 4096
#define BL (BB*LL)     // 8188

__device__ float g_y[BT*D];
__device__ float g_qc[BT*D];   // q + bq + content_bias
__device__ float g_qp[BT*D];   // q + bq + pos_bias
__device__ float g_k[BT*D];
__device__ float g_v[BT*D];
__device__ float g_p[BL*D];
__device__ float g_o[BT*D];

// ---------------- helpers ----------------
__device__ __forceinline__ unsigned f2tf(float f) {
    unsigned u; asm("cvt.rna.tf32.f32 %0, %1;" : "=r"(u) : "f"(f)); return u;
}
__device__ __forceinline__ void mma_tf32(float d[4], const unsigned a[4], const unsigned b[2]) {
    asm volatile("mma.sync.aligned.m16n8k8.row.col.f32.tf32.tf32.f32 "
        "{%0,%1,%2,%3},{%4,%5,%6,%7},{%8,%9},{%0,%1,%2,%3};\n"
        : "+f"(d[0]), "+f"(d[1]), "+f"(d[2]), "+f"(d[3])
        : "r"(a[0]), "r"(a[1]), "r"(a[2]), "r"(a[3]), "r"(b[0]), "r"(b[1]));
}
__device__ __forceinline__ void cpasync16(void* dst, const void* src, bool pred) {
    unsigned d = (unsigned)__cvta_generic_to_shared(dst);
    int sz = pred ? 16 : 0;
    asm volatile("cp.async.cg.shared.global [%0], [%1], 16, %2;\n"
                 :: "r"(d), "l"(src), "r"(sz));
}

// ---------------- LayerNorm ----------------
__global__ void ln_kernel(const float* __restrict__ x,
                          const float* __restrict__ gamma,
                          const float* __restrict__ beta) {
    int row = blockIdx.x;
    const float* xr = x + (size_t)row * D;
    float* yr = g_y + (size_t)row * D;
    int t = threadIdx.x;  // 256
    float v0 = xr[t], v1 = xr[t + 256];
    float s = v0 + v1, sq = v0 * v0 + v1 * v1;
    __shared__ float ss[8], ssq[8], mb[2];
    #pragma unroll
    for (int o = 16; o > 0; o >>= 1) {
        s  += __shfl_xor_sync(0xFFFFFFFFu, s, o);
        sq += __shfl_xor_sync(0xFFFFFFFFu, sq, o);
    }
    if ((t & 31) == 0) { ss[t >> 5] = s; ssq[t >> 5] = sq; }
    __syncthreads();
    if (t == 0) {
        float S = 0.f, SQ = 0.f;
        #pragma unroll
        for (int i = 0; i < 8; i++) { S += ss[i]; SQ += ssq[i]; }
        float mean = S * (1.0f / D);
        float var = SQ * (1.0f / D) - mean * mean;
        mb[0] = mean;
        mb[1] = rsqrtf(var + 1e-3f);
    }
    __syncthreads();
    float mean = mb[0], rstd = mb[1];
    yr[t]       = (v0 - mean) * rstd * gamma[t]       + beta[t];
    yr[t + 256] = (v1 - mean) * rstd * gamma[t + 256] + beta[t + 256];
}

// ---------------- cp.async double-buffered tf32 GEMM ----------------
// C[M,512] = A[M,512]@W[512,512]; block 128x128, 8 warps (2Mx4N), warp 64x32
struct ProjSmem {
    float As[2][128][36];
    float Bs[2][32][136];
};

__global__ void proj_mma(const float* __restrict__ A, const float* __restrict__ W,
                         const float* __restrict__ bias1,
                         const float* __restrict__ extra1, const float* __restrict__ extra2,
                         const float* __restrict__ res,
                         float* __restrict__ C1, float* __restrict__ C2, int M) {
    extern __shared__ char raw[];
    ProjSmem* S = (ProjSmem*)raw;
    int tid = threadIdx.x;
    int warp = tid >> 5, lane = tid & 31;
    int i0 = blockIdx.y * 128, j0 = blockIdx.x * 128;
    int wy = warp >> 2, wx = warp & 3;
    int g = lane >> 2, q = lane & 3;
    float acc[4][4][4] = {};

    // prefetch stage 0
    {
        int buf = 0, kk = 0;
        #pragma unroll
        for (int p = 0; p < 4; p++) {
            int idx = p * 256 + tid;
            int m = idx >> 3, c4 = (idx & 7) * 4;
            cpasync16(&S->As[buf][m][c4], &A[(size_t)(i0 + m) * 512 + kk + c4], (i0 + m) < M);
        }
        #pragma unroll
        for (int p = 0; p < 4; p++) {
            int idx = p * 256 + tid;
            int k = idx >> 5, c4 = (idx & 31) * 4;
            cpasync16(&S->Bs[buf][k][c4], &W[(size_t)(kk + k) * 512 + j0 + c4], true);
        }
        asm volatile("cp.async.commit_group;");
    }

    for (int s = 0; s < 16; s++) {
        if (s < 15) {
            int buf = (s + 1) & 1, kk = (s + 1) * 32;
            #pragma unroll
            for (int p = 0; p < 4; p++) {
                int idx = p * 256 + tid;
                int m = idx >> 3, c4 = (idx & 7) * 4;
                cpasync16(&S->As[buf][m][c4], &A[(size_t)(i0 + m) * 512 + kk + c4], (i0 + m) < M);
            }
            #pragma unroll
            for (int p = 0; p < 4; p++) {
                int idx = p * 256 + tid;
                int k = idx >> 5, c4 = (idx & 31) * 4;
                cpasync16(&S->Bs[buf][k][c4], &W[(size_t)(kk + k) * 512 + j0 + c4], true);
            }
            asm volatile("cp.async.commit_group;");
            asm volatile("cp.async.wait_group 1;");
        } else {
            asm volatile("cp.async.wait_group 0;");
        }
        __syncthreads();
        int buf = s & 1;
        #pragma unroll
        for (int k8 = 0; k8 < 4; k8++) {
            int kc = k8 * 8 + q;
            unsigned af[4][4], bf[4][2];
            #pragma unroll
            for (int mt = 0; mt < 4; mt++) {
                int r = wy * 64 + mt * 16;
                af[mt][0] = f2tf(S->As[buf][r + g][kc]);
                af[mt][1] = f2tf(S->As[buf][r + g + 8][kc]);
                af[mt][2] = f2tf(S->As[buf][r + g][kc + 4]);
                af[mt][3] = f2tf(S->As[buf][r + g + 8][kc + 4]);
            }
            #pragma unroll
            for (int nt = 0; nt < 4; nt++) {
                int c = wx * 32 + nt * 8 + g;
                bf[nt][0] = f2tf(S->Bs[buf][kc][c]);
                bf[nt][1] = f2tf(S->Bs[buf][kc + 4][c]);
            }
            #pragma unroll
            for (int mt = 0; mt < 4; mt++)
                #pragma unroll
                for (int nt = 0; nt < 4; nt++)
                    mma_tf32(acc[mt][nt], af[mt], bf[nt]);
        }
        __syncthreads();
    }
    #pragma unroll
    for (int mt = 0; mt < 4; mt++) {
        #pragma unroll
        for (int nt = 0; nt < 4; nt++) {
            int c = j0 + wx * 32 + nt * 8 + q * 2;
            float b0 = bias1 ? bias1[c] : 0.f;
            float b1 = bias1 ? bias1[c + 1] : 0.f;
            #pragma unroll
            for (int half = 0; half < 2; half++) {
                int rr = i0 + wy * 64 + mt * 16 + g + half * 8;
                if (rr >= M) continue;
                float e0 = acc[mt][nt][half * 2 + 0] + b0;
                float e1 = acc[mt][nt][half * 2 + 1] + b1;
                if (res) { e0 += res[(size_t)rr * 512 + c]; e1 += res[(size_t)rr * 512 + c + 1]; }
                float o0 = e0, o1 = e1;
                if (extra1) { o0 += extra1[c]; o1 += extra1[c + 1]; }
                *(float2*)&C1[(size_t)rr * 512 + c] = make_float2(o0, o1);
                if (C2) {
                    *(float2*)&C2[(size_t)rr * 512 + c] =
                        make_float2(e0 + extra2[c], e1 + extra2[c + 1]);
                }
            }
        }
    }
}

// ---------------- fused flash attention (content + rel-shift pos + softmax + AV) ----------------
struct FlashSmem {
    unsigned Qc[64][68];
    unsigned Qp[64][68];
    unsigned Ks[64][68];
    unsigned Vs[64][72];
    unsigned Ps[128][68];
    float    R[64][136];
    unsigned Sx[64][68];
    float    mrow[64], srow[64], crow[64];
};

__global__ void flash_kernel() {
    extern __shared__ char raw[];
    FlashSmem* S = (FlashSmem*)raw;
    int z = blockIdx.y; int b = z >> 3, h = z & 7;
    int i0 = blockIdx.x * 64;
    int tid = threadIdx.x;
    int warp = tid >> 5, lane = tid & 31;
    int wy = warp >> 1, wx = warp & 1;   // 4(M) x 2(N)
    int g = lane >> 2, q = lane & 3;

    // load Qc, Qp (resident across j-loop)
    const float* qcb = g_qc + ((size_t)(b * T + i0)) * D + h * DKK;
    const float* qpb = g_qp + ((size_t)(b * T + i0)) * D + h * DKK;
    #pragma unroll
    for (int p = 0; p < 4; p++) {
        int r = p * 16 + (tid >> 4);
        int c4 = (tid & 15) * 4;
        float4 v = *(const float4*)&qcb[(size_t)r * D + c4];
        { uint4 u = { f2tf(v.x), f2tf(v.y), f2tf(v.z), f2tf(v.w) }; *(uint4*)&S->Qc[r][c4] = u; }
        v = *(const float4*)&qpb[(size_t)r * D + c4];
        { uint4 u = { f2tf(v.x), f2tf(v.y), f2tf(v.z), f2tf(v.w) }; *(uint4*)&S->Qp[r][c4] = u; }
    }
    if (tid < 64) { S->mrow[tid] = -1e30f; S->srow[tid] = 0.f; }
    float accO[4][4] = {};
    __syncthreads();

    for (int jt = 0; jt < 16; jt++) {
        int j0 = jt * 64;
        int lb = 1024 + j0 - i0 - 63;
        const float* kb = g_k + ((size_t)(b * T + j0)) * D + h * DKK;
        const float* vb = g_v + ((size_t)(b * T + j0)) * D + h * DKK;
        #pragma unroll
        for (int p = 0; p < 4; p++) {
            int r = p * 16 + (tid >> 4);
            int c4 = (tid & 15) * 4;
            float4 v = *(const float4*)&kb[(size_t)r * D + c4];
            { uint4 u = { f2tf(v.x), f2tf(v.y), f2tf(v.z), f2tf(v.w) }; *(uint4*)&S->Ks[r][c4] = u; }
            v = *(const float4*)&vb[(size_t)r * D + c4];
            S->Vs[r][c4]     = f2tf(v.x); S->Vs[r][c4 + 1] = f2tf(v.y);
            S->Vs[r][c4 + 2] = f2tf(v.z); S->Vs[r][c4 + 3] = f2tf(v.w);
        }
        #pragma unroll
        for (int p = 0; p < 8; p++) {
            int r = p * 16 + (tid >> 4);
            int c4 = (tid & 15) * 4;
            int l = lb + r;
            l = min(max(l, 0), LL - 2);
            float4 v = *(const float4*)&g_p[((size_t)(b * LL + l)) * D + h * DKK + c4];
            uint4 u = { f2tf(v.x), f2tf(v.y), f2tf(v.z), f2tf(v.w) };
            *(uint4*)&S->Ps[r][c4] = u;
        }
        __syncthreads();

        // content + positional mma
        float accC[4][4] = {};
        float accP[8][4] = {};
        #pragma unroll
        for (int k8 = 0; k8 < 8; k8++) {
            int kc = k8 * 8 + q;
            int r = wy * 16;
            unsigned ac[4], ap[4];
            ac[0] = S->Qc[r + g][kc];     ac[1] = S->Qc[r + g + 8][kc];
            ac[2] = S->Qc[r + g][kc + 4]; ac[3] = S->Qc[r + g + 8][kc + 4];
            ap[0] = S->Qp[r + g][kc];     ap[1] = S->Qp[r + g + 8][kc];
            ap[2] = S->Qp[r + g][kc + 4]; ap[3] = S->Qp[r + g + 8][kc + 4];
            #pragma unroll
            for (int nt = 0; nt < 4; nt++) {
                int n = wx * 32 + nt * 8 + g;
                unsigned bf[2] = { S->Ks[n][kc], S->Ks[n][kc + 4] };
                mma_tf32(accC[nt], ac, bf);
            }
            #pragma unroll
            for (int nt = 0; nt < 8; nt++) {
                int n = wx * 64 + nt * 8 + g;
                unsigned bf[2] = { S->Ps[n][kc], S->Ps[n][kc + 4] };
                mma_tf32(accP[nt], ap, bf);
            }
        }
        // stash pos into R
        #pragma unroll
        for (int nt = 0; nt < 8; nt++) {
            int col = wx * 64 + nt * 8 + q * 2;
            int row = wy * 16 + g;
            S->R[row][col]     = accP[nt][0];
            S->R[row][col + 1] = accP[nt][1];
            S->R[row + 8][col]     = accP[nt][2];
            S->R[row + 8][col + 1] = accP[nt][3];
        }
        __syncthreads();
        // combine with rel-shift into Sx (scaled)
        #pragma unroll
        for (int nt = 0; nt < 4; nt++) {
            int jl = wx * 32 + nt * 8 + q * 2;
            #pragma unroll
            for (int half = 0; half < 2; half++) {
                int il = wy * 16 + g + half * 8;
                int idx = jl - il + 63;
                float v0 = (accC[nt][half * 2 + 0] + S->R[il][idx])     * 0.125f;
                float v1 = (accC[nt][half * 2 + 1] + S->R[il][idx + 1]) * 0.125f;
                S->Sx[il][jl]     = __float_as_uint(v0);
                S->Sx[il][jl + 1] = __float_as_uint(v1);
            }
        }
        __syncthreads();
        // rel_shift wraparound fix: (i=0, j=1023) uses dot(qp[1], p[0])
        if (i0 == 0 && jt == 15) {
            if (warp == 0) {
                float a0 = g_qp[((size_t)(b * T + 1)) * D + h * DKK + lane];
                float a1 = g_qp[((size_t)(b * T + 1)) * D + h * DKK + lane + 32];
                float p0 = g_p[((size_t)(b * LL)) * D + h * DKK + lane];
                float p1 = g_p[((size_t)(b * LL)) * D + h * DKK + lane + 32];
                float sdot = a0 * p0 + a1 * p1;
                #pragma unroll
                for (int o = 16; o > 0; o >>= 1)
                    sdot += __shfl_xor_sync(0xFFFFFFFFu, sdot, o);
                if (lane == 0) {
                    float old = __uint_as_float(S->Sx[0][63]);
                    S->Sx[0][63] = __float_as_uint(old + 0.125f * (sdot - S->R[0][126]));
                }
            }
            __syncthreads();
        }
        // online softmax: 4 threads per row
        {
            int row = tid >> 2, seg = tid & 3;
            float vals[16];
            float tmax = -1e30f;
            #pragma unroll
            for (int i = 0; i < 16; i++) {
                vals[i] = __uint_as_float(S->Sx[row][seg * 16 + i]);
                tmax = fmaxf(tmax, vals[i]);
            }
            tmax = fmaxf(tmax, __shfl_xor_sync(0xFFFFFFFFu, tmax, 1));
            tmax = fmaxf(tmax, __shfl_xor_sync(0xFFFFFFFFu, tmax, 2));
            float mold = S->mrow[row];
            float mnew = fmaxf(mold, tmax);
            float c = __expf(mold - mnew);
            float sum = 0.f;
            #pragma unroll
            for (int i = 0; i < 16; i++) {
                float e = __expf(vals[i] - mnew);
                sum += e;
                S->Sx[row][seg * 16 + i] = f2tf(e);
            }
            sum += __shfl_xor_sync(0xFFFFFFFFu, sum, 1);
            sum += __shfl_xor_sync(0xFFFFFFFFu, sum, 2);
            if (seg == 0) {
                S->mrow[row] = mnew;
                S->srow[row] = S->srow[row] * c + sum;
                S->crow[row] = c;
            }
        }
        __syncthreads();
        // rescale accO and accumulate P@V
        {
            float c0 = S->crow[wy * 16 + g];
            float c1 = S->crow[wy * 16 + g + 8];
            #pragma unroll
            for (int nt = 0; nt < 4; nt++) {
                accO[nt][0] *= c0; accO[nt][1] *= c0;
                accO[nt][2] *= c1; accO[nt][3] *= c1;
            }
            #pragma unroll
            for (int k8 = 0; k8 < 8; k8++) {
                int kc = k8 * 8 + q;
                int r = wy * 16;
                unsigned a[4];
                a[0] = S->Sx[r + g][kc];     a[1] = S->Sx[r + g + 8][kc];
                a[2] = S->Sx[r + g][kc + 4]; a[3] = S->Sx[r + g + 8][kc + 4];
                #pragma unroll
                for (int nt = 0; nt < 4; nt++) {
                    int n = wx * 32 + nt * 8 + g;
                    unsigned bf[2] = { S->Vs[kc][n], S->Vs[kc + 4][n] };
                    mma_tf32(accO[nt], a, bf);
                }
            }
        }
        __syncthreads();
    }
    // finalize: divide by srow, write g_o
    float inv0 = 1.f / S->srow[wy * 16 + g];
    float inv1 = 1.f / S->srow[wy * 16 + g + 8];
    #pragma unroll
    for (int nt = 0; nt < 4; nt++) {
        int col = h * DKK + wx * 32 + nt * 8 + q * 2;
        int r0 = i0 + wy * 16 + g;
        *(float2*)&g_o[((size_t)(b * T + r0)) * D + col] =
            make_float2(accO[nt][0] * inv0, accO[nt][1] * inv0);
        *(float2*)&g_o[((size_t)(b * T + r0 + 8)) * D + col] =
            make_float2(accO[nt][2] * inv1, accO[nt][3] * inv1);
    }
}

extern "C" void kernel_launch(void* const* d_in, const int* in_sizes, int n_in,
                              void* d_out, int out_size) {
    const float* x     = (const float*)d_in[0];
    const float* pos   = (const float*)d_in[1];
    const float* cb    = (const float*)d_in[2];
    const float* pb    = (const float*)d_in[3];
    const float* gamma = (const float*)d_in[4];
    const float* beta  = (const float*)d_in[5];
    const float* Wq    = (const float*)d_in[6];
    const float* bq    = (const float*)d_in[7];
    const float* Wk    = (const float*)d_in[8];
    const float* bk    = (const float*)d_in[9];
    const float* Wv    = (const float*)d_in[10];
    const float* bv    = (const float*)d_in[11];
    const float* Wp    = (const float*)d_in[12];
    const float* Wo    = (const float*)d_in[13];
    const float* bo    = (const float*)d_in[14];
    float* out = (float*)d_out;

    float *y, *qc, *qp, *k, *v, *p, *o;
    cudaGetSymbolAddress((void**)&y,  g_y);
    cudaGetSymbolAddress((void**)&qc, g_qc);
    cudaGetSymbolAddress((void**)&qp, g_qp);
    cudaGetSymbolAddress((void**)&k,  g_k);
    cudaGetSymbolAddress((void**)&v,  g_v);
    cudaGetSymbolAddress((void**)&p,  g_p);
    cudaGetSymbolAddress((void**)&o,  g_o);

    static int attr_done = 0;
    cudaFuncSetAttribute(proj_mma, cudaFuncAttributeMaxDynamicSharedMemorySize,
                         (int)sizeof(ProjSmem));
    cudaFuncSetAttribute(flash_kernel, cudaFuncAttributeMaxDynamicSharedMemorySize,
                         (int)sizeof(FlashSmem));
    (void)attr_done;

    // 1. LayerNorm
    ln_kernel<<<BT, 256>>>(x, gamma, beta);

    // 2. projections (tf32 mma, cp.async pipelined)
    dim3 g4(4, 32);
    proj_mma<<<g4, 256, sizeof(ProjSmem)>>>(y, Wq, bq, cb, pb, nullptr, qc, qp, BT);
    proj_mma<<<g4, 256, sizeof(ProjSmem)>>>(y, Wk, bk, nullptr, nullptr, nullptr, k, nullptr, BT);
    proj_mma<<<g4, 256, sizeof(ProjSmem)>>>(y, Wv, bv, nullptr, nullptr, nullptr, v, nullptr, BT);
    proj_mma<<<dim3(4, 64), 256, sizeof(ProjSmem)>>>(pos, Wp, nullptr, nullptr, nullptr, nullptr, p, nullptr, BL);

    // 3-5. fused flash attention
    flash_kernel<<<dim3(16, 32), 256, sizeof(FlashSmem)>>>();

    // 6. output projection + bias + residual
    proj_mma<<<g4, 256, sizeof(ProjSmem)>>>(o, Wo, bo, nullptr, nullptr, x, out, nullptr, BT);
}